// round 1
// baseline (speedup 1.0000x reference)
#include <cuda_runtime.h>
#include <math.h>

#define NB      4
#define IN_CHAN 128
#define HW      3136
#define HWP     3328      // padded to 13*256
#define OC      32
#define QC      8
#define D       16        // reduced score dim and value dim
#define JSPLIT  14
#define JLEN    (HW / JSPLIT)   // 224
#define TJ      32
#define BN_EPS  1e-5f

// ---------------- scratch (device globals; no allocation allowed) ----------------
__device__ __align__(16) float g_A[NB][HWP][D];                 // [q + rk ; rq]
__device__ __align__(16) float g_B[NB][HWP][D];                 // [k ; q]
__device__ __align__(16) float g_V[NB][HWP][D];                 // v + rv
__device__ __align__(16) float g_pacc[JSPLIT][NB][HWP][D];      // partial sum(e^s * v)
__device__ __align__(16) float g_pl[JSPLIT][NB][HWP];           // partial sum(e^s)

// ======================================================================
// Kernel 1: QKV 1x1 conv + BN fold + build A/B/Vext (padded rows zeroed)
// grid: (HWP/128, NB), block: 128
// ======================================================================
__global__ __launch_bounds__(128)
void qkv_kernel(const float* __restrict__ x, const float* __restrict__ w,
                const float* __restrict__ bq, const float* __restrict__ gamma,
                const float* __restrict__ beta, const float* __restrict__ mean,
                const float* __restrict__ var,
                const float* __restrict__ rq, const float* __restrict__ rk,
                const float* __restrict__ rv)
{
    __shared__ float sw[IN_CHAN][OC];     // transposed weights [c][o]
    __shared__ float sscale[OC], sbias[OC];

    const int tid = threadIdx.x;
    for (int idx = tid; idx < IN_CHAN * OC; idx += 128) {
        int o = idx / IN_CHAN, c = idx % IN_CHAN;
        sw[c][o] = w[o * IN_CHAN + c];
    }
    if (tid < OC) {
        float sc = gamma[tid] * rsqrtf(var[tid] + BN_EPS);
        sscale[tid] = sc;
        sbias[tid]  = (bq[tid] - mean[tid]) * sc + beta[tid];
    }
    __syncthreads();

    const int n   = blockIdx.y;
    const int pix = blockIdx.x * 128 + tid;

    float* Ap = &g_A[n][pix][0];
    float* Bp = &g_B[n][pix][0];
    float* Vp = &g_V[n][pix][0];

    if (pix >= HW) {
        // zero padded rows so attention reads are benign
        float4 z = make_float4(0.f, 0.f, 0.f, 0.f);
        #pragma unroll
        for (int q4 = 0; q4 < 4; q4++) {
            reinterpret_cast<float4*>(Ap)[q4] = z;
            reinterpret_cast<float4*>(Bp)[q4] = z;
            reinterpret_cast<float4*>(Vp)[q4] = z;
        }
        return;
    }

    float acc[OC];
    #pragma unroll
    for (int o = 0; o < OC; o++) acc[o] = 0.f;

    const float* xp = x + (size_t)n * IN_CHAN * HW + pix;
    #pragma unroll 4
    for (int c = 0; c < IN_CHAN; c++) {
        float xv = __ldg(xp + (size_t)c * HW);
        #pragma unroll
        for (int o = 0; o < OC; o++) acc[o] = fmaf(xv, sw[c][o], acc[o]);
    }

    float r[OC];
    #pragma unroll
    for (int o = 0; o < OC; o++) r[o] = fmaf(acc[o], sscale[o], sbias[o]);

    // A = [q + rk_col ; rq_col]
    float av[D], bv[D], vv[D];
    #pragma unroll
    for (int c = 0; c < QC; c++) {
        av[c]      = r[c] + __ldg(rk + (size_t)c * HW + pix);
        av[QC + c] = __ldg(rq + (size_t)c * HW + pix);
        bv[c]      = r[QC + c];   // k
        bv[QC + c] = r[c];        // q
    }
    #pragma unroll
    for (int c = 0; c < 2 * QC; c++)
        vv[c] = r[2 * QC + c] + __ldg(rv + (size_t)c * HW + pix);

    #pragma unroll
    for (int q4 = 0; q4 < 4; q4++) {
        reinterpret_cast<float4*>(Ap)[q4] = reinterpret_cast<float4*>(av)[q4];
        reinterpret_cast<float4*>(Bp)[q4] = reinterpret_cast<float4*>(bv)[q4];
        reinterpret_cast<float4*>(Vp)[q4] = reinterpret_cast<float4*>(vv)[q4];
    }
}

// ======================================================================
// Kernel 2: attention core. No-max softmax (scores bounded ~|30| << 88),
// so j-split partials (sum e^s * v, sum e^s) just add in the combiner.
// grid: (13 i-tiles, JSPLIT, NB), block: 128; each thread owns 2 queries.
// ======================================================================
__global__ __launch_bounds__(128)
void attn_kernel()
{
    __shared__ __align__(16) float sB[TJ * D];
    __shared__ __align__(16) float sV[TJ * D];

    const int tid   = threadIdx.x;
    const int itile = blockIdx.x;
    const int js    = blockIdx.y;
    const int n     = blockIdx.z;

    const int i0 = itile * 256 + tid;
    const int i1 = i0 + 128;

    float a0[D], a1[D];
    #pragma unroll
    for (int q4 = 0; q4 < 4; q4++) {
        reinterpret_cast<float4*>(a0)[q4] =
            reinterpret_cast<const float4*>(&g_A[n][i0][0])[q4];
        reinterpret_cast<float4*>(a1)[q4] =
            reinterpret_cast<const float4*>(&g_A[n][i1][0])[q4];
    }

    float acc0[D], acc1[D];
    #pragma unroll
    for (int d = 0; d < D; d++) { acc0[d] = 0.f; acc1[d] = 0.f; }
    float l0 = 0.f, l1 = 0.f;

    const int jbase = js * JLEN;
    for (int t = 0; t < JLEN / TJ; t++) {
        const int j0 = jbase + t * TJ;
        // cooperative tile load: TJ*D = 512 floats = 128 float4 -> 1 per thread
        reinterpret_cast<float4*>(sB)[tid] =
            reinterpret_cast<const float4*>(&g_B[n][j0][0])[tid];
        reinterpret_cast<float4*>(sV)[tid] =
            reinterpret_cast<const float4*>(&g_V[n][j0][0])[tid];
        __syncthreads();

        #pragma unroll 2
        for (int jj = 0; jj < TJ; jj++) {
            const float* b = &sB[jj * D];
            float s0a = 0.f, s0b = 0.f, s1a = 0.f, s1b = 0.f;
            #pragma unroll
            for (int d = 0; d < D; d += 2) {
                s0a = fmaf(a0[d],     b[d],     s0a);
                s0b = fmaf(a0[d + 1], b[d + 1], s0b);
                s1a = fmaf(a1[d],     b[d],     s1a);
                s1b = fmaf(a1[d + 1], b[d + 1], s1b);
            }
            float p0 = __expf(s0a + s0b);
            float p1 = __expf(s1a + s1b);
            l0 += p0; l1 += p1;
            const float* v = &sV[jj * D];
            #pragma unroll
            for (int d = 0; d < D; d++) {
                acc0[d] = fmaf(p0, v[d], acc0[d]);
                acc1[d] = fmaf(p1, v[d], acc1[d]);
            }
        }
        __syncthreads();
    }

    #pragma unroll
    for (int q4 = 0; q4 < 4; q4++) {
        reinterpret_cast<float4*>(&g_pacc[js][n][i0][0])[q4] =
            reinterpret_cast<float4*>(acc0)[q4];
        reinterpret_cast<float4*>(&g_pacc[js][n][i1][0])[q4] =
            reinterpret_cast<float4*>(acc1)[q4];
    }
    g_pl[js][n][i0] = l0;
    g_pl[js][n][i1] = l1;
}

// ======================================================================
// Kernel 3: combine j-split partials, normalize, 2x2 avg pool.
// out[n][c][ph][pw], one thread per output element.
// ======================================================================
__global__ void combine_kernel(float* __restrict__ out)
{
    const int idx = blockIdx.x * blockDim.x + threadIdx.x;
    const int TOT = NB * 2 * QC * 28 * 28;
    if (idx >= TOT) return;
    int pw = idx % 28;
    int t  = idx / 28;
    int ph = t % 28; t /= 28;
    int c  = t % (2 * QC);
    int n  = t / (2 * QC);

    float r = 0.f;
    #pragma unroll
    for (int sh = 0; sh < 2; sh++) {
        #pragma unroll
        for (int sw_ = 0; sw_ < 2; sw_++) {
            int i = (2 * ph + sh) * 56 + (2 * pw + sw_);
            float num = 0.f, den = 0.f;
            #pragma unroll
            for (int s = 0; s < JSPLIT; s++) {
                num += g_pacc[s][n][i][c];
                den += g_pl[s][n][i];
            }
            r += num / den;
        }
    }
    out[idx] = 0.25f * r;
}

// ======================================================================
extern "C" void kernel_launch(void* const* d_in, const int* in_sizes, int n_in,
                              void* d_out, int out_size)
{
    const float* x     = (const float*)d_in[0];
    const float* w     = (const float*)d_in[1];
    const float* bq    = (const float*)d_in[2];
    const float* gamma = (const float*)d_in[3];
    const float* beta  = (const float*)d_in[4];
    const float* mean  = (const float*)d_in[5];
    const float* var   = (const float*)d_in[6];
    const float* rq    = (const float*)d_in[7];
    const float* rk    = (const float*)d_in[8];
    const float* rv    = (const float*)d_in[9];
    float* out = (float*)d_out;

    dim3 g1(HWP / 128, NB);
    qkv_kernel<<<g1, 128>>>(x, w, bq, gamma, beta, mean, var, rq, rk, rv);

    dim3 g2(HWP / 256, JSPLIT, NB);
    attn_kernel<<<g2, 128>>>();

    const int TOT = NB * 2 * QC * 28 * 28;
    combine_kernel<<<(TOT + 255) / 256, 256>>>(out);
}